// round 11
// baseline (speedup 1.0000x reference)
#include <cuda_runtime.h>
#include <math.h>

// ---- problem constants -----------------------------------------------------
constexpr int NN  = 62;     // nodes per graph
constexpr int NP  = 64;     // padded nodes
constexpr int BB  = 512;    // graphs
constexpr int FIN = 128;    // input features
constexpr int KH  = 64;     // k-half for staged stage-1
constexpr int HH  = 64;     // hidden
constexpr int CC  = 3;      // classes

// smem map (floats). sBuf holds {XT half, W1T half} in stages 1a/1b, then A2.
// All inner-loop loads are within a single 64-float row -> stride 64 exact,
// no padding, no swizzle, no conflicts.
constexpr int SZ_BUF  = 2 * KH * NP;   // 8192 (XT 64x64 + W1T 64x64) / A2 aliased
constexpr int SZ_M    = NP * HH;       // 4096
constexpr int SZ_B1   = HH;            // 64
constexpr int SZ_POOL = 16 * HH;       // 1024
constexpr int SZ_PD   = HH;            // 64
constexpr int SMEM_FLOATS = SZ_BUF + SZ_M + SZ_B1 + SZ_POOL + SZ_PD;  // 13440 = 52.5KB

__device__ float g_A2[NP * NP];      // A^2 plain [64][64], rows/cols >=62 zero
__device__ float g_W1T[FIN * HH];    // W1 transposed [k][h]

// ---- prep: 64 blocks x 64 threads. Block b -> A2 row b + W1T scatter. -----
__global__ void prep_kernel(const float* __restrict__ tril,
                            const float* __restrict__ W1) {
    __shared__ float A[NP][NP];
    __shared__ float dv[NP];
    __shared__ float d2[NP];
    __shared__ float trow[NP];
    const int j = threadIdx.x;    // 0..63
    const int b = blockIdx.x;     // 0..63

    for (int idx = j; idx < NP * NP; idx += 64) {
        int i = idx >> 6, jj = idx & 63;
        float v = 0.f;
        if (i < NN && jj < NN) {
            int a_ = i > jj ? i : jj;
            int b_ = i > jj ? jj : i;
            v = tril[a_ * (a_ + 1) / 2 + b_];
        }
        A[i][jj] = v;
    }
    __syncthreads();

    {
        float s = 0.f;
        #pragma unroll 4
        for (int k = 0; k < NP; ++k) s += fabsf(A[j][k]);
        float di = s > 0.f ? rsqrtf(s) : 0.f;   // rows >=62: s=0 -> di=0
        dv[j] = di;
        d2[j] = di * di;
    }
    __syncthreads();

    trow[j] = A[b][j] * d2[j];
    __syncthreads();

    {
        float s = 0.f;
        #pragma unroll 4
        for (int k = 0; k < NP; ++k) s += trow[k] * A[k][j];
        g_A2[b * NP + j] = dv[b] * s * dv[j];   // padded rows/cols -> 0
    }

    // W1T[k][h]: block b handles h = b
    for (int k = j; k < FIN; k += 64)
        g_W1T[k * HH + b] = W1[b * FIN + k];
}

// ---- main: 512 CTAs x 256 threads; single wave @ 4 CTAs/SM ------------------
__global__ __launch_bounds__(256, 4)
void graph_kernel(const float* __restrict__ x,
                  const float* __restrict__ b1,
                  const float* __restrict__ W2,
                  const float* __restrict__ b2,
                  float* __restrict__ out) {
    extern __shared__ float sm[];
    float* sXT     = sm;                      // [KH][64]  (phase A/B)
    float* sW1T    = sm + KH * NP;            // [KH][64]  (phase A/B)
    float* sA2     = sm;                      // [64][64]  (phase C, aliases sBuf)
    float* sM      = sm + SZ_BUF;             // [64 node][64 h]
    float* sB1     = sM   + SZ_M;             // 64
    float* sPool   = sB1  + SZ_B1;            // [16][64]
    float* sPooled = sPool + SZ_POOL;         // 64

    const int tid = threadIdx.x;
    const int g   = blockIdx.x;
    const int tr  = tid >> 4;      // 0..15 row group
    const int tc  = tid & 15;      // 0..15 col group
    const int r0  = tr * 4;
    const int c0  = tc * 4;

    const float* xg = x + (size_t)g * NN * FIN;
    if (tid < HH) sB1[tid] = b1[tid];

    float acc[4][4];
    #pragma unroll
    for (int r = 0; r < 4; ++r)
        #pragma unroll
        for (int c = 0; c < 4; ++c) acc[r][c] = 0.f;

    // ================= stage 1: M = X @ W1^T, two k-halves =================
    #pragma unroll 1
    for (int ph = 0; ph < 2; ++ph) {
        // load XT half (transpose from global) + W1T half
        for (int t = tid; t < NP * (KH / 4); t += 256) {   // 1024 iters
            int i  = t & 63;
            int kq = t >> 6;                               // 0..15
            float4 v = make_float4(0.f, 0.f, 0.f, 0.f);
            if (i < NN)
                v = *(const float4*)(xg + (size_t)i * FIN + ph * KH + kq * 4);
            sXT[(kq * 4 + 0) * NP + i] = v.x;              // distinct i -> no conflict
            sXT[(kq * 4 + 1) * NP + i] = v.y;
            sXT[(kq * 4 + 2) * NP + i] = v.z;
            sXT[(kq * 4 + 3) * NP + i] = v.w;
        }
        const float4* wsrc = (const float4*)(g_W1T + ph * KH * HH);
        for (int t = tid; t < KH * HH / 4; t += 256)
            ((float4*)sW1T)[t] = wsrc[t];
        __syncthreads();

        #pragma unroll 2
        for (int k = 0; k < KH; ++k) {
            float4 xv = *(const float4*)(sXT  + k * NP + r0);  // 2-addr broadcast
            float4 wv = *(const float4*)(sW1T + k * NP + c0);  // 256B contiguous
            float xr[4] = {xv.x, xv.y, xv.z, xv.w};
            float wc[4] = {wv.x, wv.y, wv.z, wv.w};
            #pragma unroll
            for (int r = 0; r < 4; ++r)
                #pragma unroll
                for (int c = 0; c < 4; ++c)
                    acc[r][c] += xr[r] * wc[c];
        }
        __syncthreads();   // done reading this half before overwrite
    }
    // write M[node][h]
    #pragma unroll
    for (int r = 0; r < 4; ++r)
        *(float4*)(sM + (r0 + r) * HH + c0) =
            make_float4(acc[r][0], acc[r][1], acc[r][2], acc[r][3]);
    __syncthreads();

    // ================= phase C: load A2 into sBuf ===========================
    {
        const float4* a24 = (const float4*)g_A2;
        for (int t = tid; t < NP * NP / 4; t += 256) ((float4*)sA2)[t] = a24[t];
    }
    __syncthreads();

    // ================= stage 2: Y = A2 @ M (A2 symmetric), relu+b1, pool ====
    #pragma unroll
    for (int r = 0; r < 4; ++r)
        #pragma unroll
        for (int c = 0; c < 4; ++c) acc[r][c] = 0.f;

    #pragma unroll 2
    for (int k = 0; k < NP; ++k) {
        float4 av = *(const float4*)(sA2 + k * NP + r0);   // A2[k][r] == A2[r][k]
        float4 mv = *(const float4*)(sM  + k * HH + c0);
        float ar[4] = {av.x, av.y, av.z, av.w};
        float mc[4] = {mv.x, mv.y, mv.z, mv.w};
        #pragma unroll
        for (int r = 0; r < 4; ++r)
            #pragma unroll
            for (int c = 0; c < 4; ++c)
                acc[r][c] += ar[r] * mc[c];
    }

    {
        float4 bb = *(const float4*)(sB1 + c0);
        float part[4] = {0.f, 0.f, 0.f, 0.f};
        #pragma unroll
        for (int r = 0; r < 4; ++r) {
            if (r0 + r < NN) {   // padded rows: Y=0 but relu(b1)!=0 -> mask
                part[0] += fmaxf(acc[r][0] + bb.x, 0.f);
                part[1] += fmaxf(acc[r][1] + bb.y, 0.f);
                part[2] += fmaxf(acc[r][2] + bb.z, 0.f);
                part[3] += fmaxf(acc[r][3] + bb.w, 0.f);
            }
        }
        *(float4*)(sPool + tr * HH + c0) =
            make_float4(part[0], part[1], part[2], part[3]);
    }
    __syncthreads();

    // ================= stage 3: pool reduce -> latent; head + log_softmax ===
    if (tid < HH) {
        float p = 0.f;
        #pragma unroll
        for (int t = 0; t < 16; ++t) p += sPool[t * HH + tid];
        sPooled[tid] = p;
        out[(size_t)g * HH + tid] = p;          // latent_v
    }
    __syncthreads();

    if (tid < 32) {
        float p0 = sPooled[tid], p1 = sPooled[tid + 32];
        float l[CC];
        #pragma unroll
        for (int cc = 0; cc < CC; ++cc) {
            l[cc] = p0 * W2[cc * HH + tid] + p1 * W2[cc * HH + tid + 32];
            #pragma unroll
            for (int off = 16; off; off >>= 1)
                l[cc] += __shfl_xor_sync(0xffffffffu, l[cc], off);
        }
        if (tid == 0) {
            float l0 = l[0] + b2[0];
            float l1 = l[1] + b2[1];
            float l2 = l[2] + b2[2];
            float m  = fmaxf(l0, fmaxf(l1, l2));
            float lse = m + logf(expf(l0 - m) + expf(l1 - m) + expf(l2 - m));
            float* lp = out + (size_t)BB * HH + (size_t)g * CC;
            lp[0] = l0 - lse;
            lp[1] = l1 - lse;
            lp[2] = l2 - lse;
        }
    }
}

// ---- launch -----------------------------------------------------------------
extern "C" void kernel_launch(void* const* d_in, const int* in_sizes, int n_in,
                              void* d_out, int out_size) {
    (void)in_sizes; (void)n_in; (void)out_size;
    const float* x    = (const float*)d_in[0];
    const float* tril = (const float*)d_in[1];
    const float* W1   = (const float*)d_in[2];
    const float* b1   = (const float*)d_in[3];
    const float* W2   = (const float*)d_in[4];
    const float* b2   = (const float*)d_in[5];
    float* out = (float*)d_out;

    const int smem_bytes = SMEM_FLOATS * (int)sizeof(float);   // 53760
    cudaFuncSetAttribute(graph_kernel,
                         cudaFuncAttributeMaxDynamicSharedMemorySize, smem_bytes);

    prep_kernel<<<64, 64>>>(tril, W1);
    graph_kernel<<<BB, 256, smem_bytes>>>(x, b1, W2, b2, out);
}

// round 12
// speedup vs baseline: 1.1141x; 1.1141x over previous
#include <cuda_runtime.h>
#include <math.h>

// ---- problem constants -----------------------------------------------------
constexpr int NN  = 62;     // nodes per graph
constexpr int NP  = 64;     // padded nodes
constexpr int BB  = 512;    // graphs
constexpr int FIN = 128;    // input features
constexpr int KH  = 64;     // k-half for staged stage-1
constexpr int HH  = 64;     // hidden
constexpr int CC  = 3;      // classes

// smem map (floats): sBuf holds {XT half, W1T half} during stage 1, A2 aliases
// the XT region in stage 2. All inner-loop loads are within one 64-float row.
constexpr int SZ_BUF  = 2 * KH * NP;   // 8192
constexpr int SZ_M    = NP * HH;       // 4096
constexpr int SZ_B1   = HH;            // 64
constexpr int SZ_POOL = 16 * HH;       // 1024
constexpr int SZ_PD   = HH;            // 64
constexpr int SMEM_FLOATS = SZ_BUF + SZ_M + SZ_B1 + SZ_POOL + SZ_PD;  // 13440 = 52.5KB

__device__ float g_A2[NP * NP];      // A^2 plain [64][64], rows/cols >=62 zero
__device__ float g_W1T[FIN * HH];    // W1 transposed [k][h]

__device__ __forceinline__ void fma2(unsigned long long& d,
                                     unsigned long long a,
                                     unsigned long long b) {
    asm("fma.rn.f32x2 %0, %1, %2, %0;" : "+l"(d) : "l"(a), "l"(b));
}
__device__ __forceinline__ unsigned long long dup2(float v) {
    unsigned long long r;
    asm("mov.b64 %0, {%1, %1};" : "=l"(r) : "f"(v));
    return r;
}
__device__ __forceinline__ void unpack2(unsigned long long v, float& lo, float& hi) {
    asm("mov.b64 {%0,%1}, %2;" : "=f"(lo), "=f"(hi) : "l"(v));
}

// ---- prep: 64 blocks x 64 threads. Block b -> A2 row b + W1T scatter. ------
__global__ void prep_kernel(const float* __restrict__ tril,
                            const float* __restrict__ W1) {
    __shared__ float A[NP][NP];
    __shared__ float dv[NP];
    __shared__ float d2[NP];
    __shared__ float trow[NP];
    const int j = threadIdx.x;    // 0..63
    const int b = blockIdx.x;     // 0..63

    for (int idx = j; idx < NP * NP; idx += 64) {
        int i = idx >> 6, jj = idx & 63;
        float v = 0.f;
        if (i < NN && jj < NN) {
            int a_ = i > jj ? i : jj;
            int b_ = i > jj ? jj : i;
            v = tril[a_ * (a_ + 1) / 2 + b_];
        }
        A[i][jj] = v;
    }
    __syncthreads();

    {
        float s = 0.f;
        #pragma unroll 4
        for (int k = 0; k < NP; ++k) s += fabsf(A[j][k]);
        float di = s > 0.f ? rsqrtf(s) : 0.f;
        dv[j] = di;
        d2[j] = di * di;
    }
    __syncthreads();

    trow[j] = A[b][j] * d2[j];
    __syncthreads();

    {
        float s = 0.f;
        #pragma unroll 4
        for (int k = 0; k < NP; ++k) s += trow[k] * A[k][j];
        g_A2[b * NP + j] = dv[b] * s * dv[j];
    }

    for (int k = j; k < FIN; k += 64)
        g_W1T[k * HH + b] = W1[b * FIN + k];
}

// ---- main: 512 CTAs x 256 threads; FFMA2 row-pairs + reg-prefetch ----------
__global__ __launch_bounds__(256, 4)
void graph_kernel(const float* __restrict__ x,
                  const float* __restrict__ b1,
                  const float* __restrict__ W2,
                  const float* __restrict__ b2,
                  float* __restrict__ out) {
    extern __shared__ float sm[];
    float* sXT     = sm;                      // [KH][64]  (stage 1)
    float* sW1T    = sm + KH * NP;            // [KH][64]  (stage 1)
    float* sA2     = sm;                      // [64][64]  (stage 2, aliases sXT)
    float* sM      = sm + SZ_BUF;             // [node][h]
    float* sB1     = sM   + SZ_M;
    float* sPool   = sB1  + SZ_B1;
    float* sPooled = sPool + SZ_POOL;

    const int tid = threadIdx.x;
    const int g   = blockIdx.x;
    const int tr  = tid >> 4;      // 0..15
    const int tc  = tid & 15;      // 0..15
    const int r0  = tr * 4;
    const int c0  = tc * 4;

    const float* xg = x + (size_t)g * NN * FIN;
    if (tid < HH) sB1[tid] = b1[tid];

    // staging index split: iterations t = tid + j*256 have node i = tid&63
    // (256 % 64 == 0) and kq = (tid>>6) + 4j.
    const int iS  = tid & 63;
    const int kqS = tid >> 6;
    const bool iOK = iS < NN;

    // ---- stage half-0 of X (transpose) + W1T half-0 ----
    #pragma unroll
    for (int j = 0; j < 4; ++j) {
        int kq = kqS + 4 * j;
        float4 v = iOK ? *(const float4*)(xg + (size_t)iS * FIN + kq * 4)
                       : make_float4(0.f, 0.f, 0.f, 0.f);
        sXT[(kq * 4 + 0) * NP + iS] = v.x;
        sXT[(kq * 4 + 1) * NP + iS] = v.y;
        sXT[(kq * 4 + 2) * NP + iS] = v.z;
        sXT[(kq * 4 + 3) * NP + iS] = v.w;
    }
    {
        const float4* wsrc = (const float4*)g_W1T;
        #pragma unroll
        for (int j = 0; j < 4; ++j)
            ((float4*)sW1T)[tid + j * 256] = wsrc[tid + j * 256];
    }
    __syncthreads();

    unsigned long long acc[2][4];
    #pragma unroll
    for (int p = 0; p < 2; ++p)
        #pragma unroll
        for (int c = 0; c < 4; ++c) acc[p][c] = 0ull;

    // prefetch X half-1 into registers (DRAM latency overlaps compute below)
    float4 xpre[4];
    #pragma unroll
    for (int j = 0; j < 4; ++j) {
        int kq = kqS + 4 * j;
        xpre[j] = iOK ? *(const float4*)(xg + (size_t)iS * FIN + KH + kq * 4)
                      : make_float4(0.f, 0.f, 0.f, 0.f);
    }

    // ---- compute half-0:  acc += XT-rowpairs * dup(w) ----
    #pragma unroll 2
    for (int k = 0; k < KH; ++k) {
        ulonglong2 xv = *(const ulonglong2*)(sXT + k * NP + r0);
        float4 wv = *(const float4*)(sW1T + k * NP + c0);
        unsigned long long w0 = dup2(wv.x), w1 = dup2(wv.y),
                           w2d = dup2(wv.z), w3 = dup2(wv.w);
        fma2(acc[0][0], xv.x, w0); fma2(acc[1][0], xv.y, w0);
        fma2(acc[0][1], xv.x, w1); fma2(acc[1][1], xv.y, w1);
        fma2(acc[0][2], xv.x, w2d); fma2(acc[1][2], xv.y, w2d);
        fma2(acc[0][3], xv.x, w3); fma2(acc[1][3], xv.y, w3);
    }
    __syncthreads();   // half-0 fully read

    // ---- stage half-1 (X from prefetched regs) + W1T half-1 ----
    #pragma unroll
    for (int j = 0; j < 4; ++j) {
        int kq = kqS + 4 * j;
        sXT[(kq * 4 + 0) * NP + iS] = xpre[j].x;
        sXT[(kq * 4 + 1) * NP + iS] = xpre[j].y;
        sXT[(kq * 4 + 2) * NP + iS] = xpre[j].z;
        sXT[(kq * 4 + 3) * NP + iS] = xpre[j].w;
    }
    {
        const float4* wsrc = (const float4*)(g_W1T + KH * HH);
        #pragma unroll
        for (int j = 0; j < 4; ++j)
            ((float4*)sW1T)[tid + j * 256] = wsrc[tid + j * 256];
    }
    __syncthreads();

    // prefetch A2 into registers (consumed after half-1 compute)
    float4 apre[4];
    {
        const float4* a24 = (const float4*)g_A2;
        #pragma unroll
        for (int j = 0; j < 4; ++j) apre[j] = a24[tid + j * 256];
    }

    // ---- compute half-1 ----
    #pragma unroll 2
    for (int k = 0; k < KH; ++k) {
        ulonglong2 xv = *(const ulonglong2*)(sXT + k * NP + r0);
        float4 wv = *(const float4*)(sW1T + k * NP + c0);
        unsigned long long w0 = dup2(wv.x), w1 = dup2(wv.y),
                           w2d = dup2(wv.z), w3 = dup2(wv.w);
        fma2(acc[0][0], xv.x, w0); fma2(acc[1][0], xv.y, w0);
        fma2(acc[0][1], xv.x, w1); fma2(acc[1][1], xv.y, w1);
        fma2(acc[0][2], xv.x, w2d); fma2(acc[1][2], xv.y, w2d);
        fma2(acc[0][3], xv.x, w3); fma2(acc[1][3], xv.y, w3);
    }

    // write M[node][h]: unpack row pairs
    {
        float m0[4], m1[4], m2[4], m3[4];
        #pragma unroll
        for (int c = 0; c < 4; ++c) {
            unpack2(acc[0][c], m0[c], m1[c]);
            unpack2(acc[1][c], m2[c], m3[c]);
        }
        __syncthreads();   // everyone done reading sXT/sW1T before A2 overwrite & M write
        *(float4*)(sM + (r0 + 0) * HH + c0) = make_float4(m0[0], m0[1], m0[2], m0[3]);
        *(float4*)(sM + (r0 + 1) * HH + c0) = make_float4(m1[0], m1[1], m1[2], m1[3]);
        *(float4*)(sM + (r0 + 2) * HH + c0) = make_float4(m2[0], m2[1], m2[2], m2[3]);
        *(float4*)(sM + (r0 + 3) * HH + c0) = make_float4(m3[0], m3[1], m3[2], m3[3]);
        #pragma unroll
        for (int j = 0; j < 4; ++j)
            ((float4*)sA2)[tid + j * 256] = apre[j];
    }
    __syncthreads();

    // ---- stage 2: Y = A2 @ M (A2 symmetric -> row read), relu+b1, pool ----
    #pragma unroll
    for (int p = 0; p < 2; ++p)
        #pragma unroll
        for (int c = 0; c < 4; ++c) acc[p][c] = 0ull;

    #pragma unroll 2
    for (int k = 0; k < NP; ++k) {
        ulonglong2 av = *(const ulonglong2*)(sA2 + k * NP + r0);  // A2[k][r]==A2[r][k]
        float4 mv = *(const float4*)(sM + k * HH + c0);
        unsigned long long m0 = dup2(mv.x), m1 = dup2(mv.y),
                           m2d = dup2(mv.z), m3 = dup2(mv.w);
        fma2(acc[0][0], av.x, m0); fma2(acc[1][0], av.y, m0);
        fma2(acc[0][1], av.x, m1); fma2(acc[1][1], av.y, m1);
        fma2(acc[0][2], av.x, m2d); fma2(acc[1][2], av.y, m2d);
        fma2(acc[0][3], av.x, m3); fma2(acc[1][3], av.y, m3);
    }

    {
        float4 bb = *(const float4*)(sB1 + c0);
        float bbv[4] = {bb.x, bb.y, bb.z, bb.w};
        float part[4] = {0.f, 0.f, 0.f, 0.f};
        #pragma unroll
        for (int p = 0; p < 2; ++p) {
            #pragma unroll
            for (int c = 0; c < 4; ++c) {
                float lo, hi;
                unpack2(acc[p][c], lo, hi);
                if (r0 + 2 * p + 0 < NN) part[c] += fmaxf(lo + bbv[c], 0.f);
                if (r0 + 2 * p + 1 < NN) part[c] += fmaxf(hi + bbv[c], 0.f);
            }
        }
        *(float4*)(sPool + tr * HH + c0) =
            make_float4(part[0], part[1], part[2], part[3]);
    }
    __syncthreads();

    // ---- stage 3: pool reduce -> latent; head + log_softmax ----
    if (tid < HH) {
        float p = 0.f;
        #pragma unroll
        for (int t = 0; t < 16; ++t) p += sPool[t * HH + tid];
        sPooled[tid] = p;
        out[(size_t)g * HH + tid] = p;          // latent_v
    }
    __syncthreads();

    if (tid < 32) {
        float p0 = sPooled[tid], p1 = sPooled[tid + 32];
        float l[CC];
        #pragma unroll
        for (int cc = 0; cc < CC; ++cc) {
            l[cc] = p0 * W2[cc * HH + tid] + p1 * W2[cc * HH + tid + 32];
            #pragma unroll
            for (int off = 16; off; off >>= 1)
                l[cc] += __shfl_xor_sync(0xffffffffu, l[cc], off);
        }
        if (tid == 0) {
            float l0 = l[0] + b2[0];
            float l1 = l[1] + b2[1];
            float l2 = l[2] + b2[2];
            float m  = fmaxf(l0, fmaxf(l1, l2));
            float lse = m + logf(expf(l0 - m) + expf(l1 - m) + expf(l2 - m));
            float* lp = out + (size_t)BB * HH + (size_t)g * CC;
            lp[0] = l0 - lse;
            lp[1] = l1 - lse;
            lp[2] = l2 - lse;
        }
    }
}

// ---- launch -----------------------------------------------------------------
extern "C" void kernel_launch(void* const* d_in, const int* in_sizes, int n_in,
                              void* d_out, int out_size) {
    (void)in_sizes; (void)n_in; (void)out_size;
    const float* x    = (const float*)d_in[0];
    const float* tril = (const float*)d_in[1];
    const float* W1   = (const float*)d_in[2];
    const float* b1   = (const float*)d_in[3];
    const float* W2   = (const float*)d_in[4];
    const float* b2   = (const float*)d_in[5];
    float* out = (float*)d_out;

    const int smem_bytes = SMEM_FLOATS * (int)sizeof(float);   // 53760
    cudaFuncSetAttribute(graph_kernel,
                         cudaFuncAttributeMaxDynamicSharedMemorySize, smem_bytes);

    prep_kernel<<<64, 64>>>(tril, W1);
    graph_kernel<<<BB, 256, smem_bytes>>>(x, b1, W2, b2, out);
}